// round 13
// baseline (speedup 1.0000x reference)
#include <cuda_runtime.h>
#include <cuda_fp16.h>
#include <cstdint>

#define N_TOK 8192
#define DIM   1024
#define NEXP  8
#define HID   256

#define BM 64
#define BN 128
#define BK 32    // K elements per tile (2 x k16 mma steps)
#define LDA 40   // padded row stride in halves: 80B, conflict-free ldmatrix
#define LDB 40

// ---- static device scratch (no allocations allowed) ----
__device__ int    g_cursor[NEXP];
__device__ int    g_token[NEXP * N_TOK];
__device__ float  g_gate [NEXP * N_TOK];
__device__ int    g_dst  [NEXP * N_TOK];               // eo row = 2*token+which
__device__ __half g_h1h[(size_t)NEXP * N_TOK * HID];   // 32 MB
__device__ __half g_h2h[(size_t)NEXP * N_TOK * HID];   // 32 MB
__device__ __half g_eoh[(size_t)2 * N_TOK * DIM];      // 32 MB token-major
__device__ __half g_w1t[(size_t)NEXP * DIM * HID];     // 4 MB  [e][N][K] half
__device__ __half g_w2t[(size_t)NEXP * HID * HID];     // 1 MB
__device__ __half g_w3t[(size_t)NEXP * HID * DIM];     // 4 MB

// ---------------------------------------------------------------------------
__device__ __forceinline__ void ldsm_x4(unsigned addr, unsigned r[4]) {
    asm volatile("ldmatrix.sync.aligned.m8n8.x4.shared.b16 {%0,%1,%2,%3}, [%4];"
                 : "=r"(r[0]), "=r"(r[1]), "=r"(r[2]), "=r"(r[3]) : "r"(addr));
}
__device__ __forceinline__ void mma_f16(float c[4], const unsigned a[4],
                                        unsigned b0, unsigned b1) {
    asm volatile(
        "mma.sync.aligned.m16n8k16.row.col.f32.f16.f16.f32 "
        "{%0,%1,%2,%3}, {%4,%5,%6,%7}, {%8,%9}, {%0,%1,%2,%3};"
        : "+f"(c[0]), "+f"(c[1]), "+f"(c[2]), "+f"(c[3])
        : "r"(a[0]), "r"(a[1]), "r"(a[2]), "r"(a[3]), "r"(b0), "r"(b1));
}
__device__ __forceinline__ unsigned pack_h2(float x, float y) {
    __half2 h = __floats2half2_rn(x, y);
    return *(unsigned*)&h;
}

// ---------------------------------------------------------------------------
// prep: zero cursors + transpose/convert weights to [e][N][K] half
// ---------------------------------------------------------------------------
__global__ void prep_kernel(const float* __restrict__ W1,
                            const float* __restrict__ W2,
                            const float* __restrict__ W3,
                            __half* __restrict__ w1t,
                            __half* __restrict__ w2t,
                            __half* __restrict__ w3t) {
    if (blockIdx.x == 0 && blockIdx.z == 0 && threadIdx.x < NEXP)
        g_cursor[threadIdx.x] = 0;

    int e = blockIdx.z;
    int bid = blockIdx.x;
    const float* src;
    __half* dst;
    int KD, ND, kt, nt;
    if (bid < 128) {
        src = W1 + (size_t)e * DIM * HID; dst = w1t + (size_t)e * DIM * HID;
        KD = DIM; ND = HID; kt = bid >> 3; nt = bid & 7;
    } else if (bid < 160) {
        int r = bid - 128;
        src = W2 + (size_t)e * HID * HID; dst = w2t + (size_t)e * HID * HID;
        KD = HID; ND = HID; kt = r >> 3; nt = r & 7;
    } else {
        int r = bid - 160;
        src = W3 + (size_t)e * HID * DIM; dst = w3t + (size_t)e * HID * DIM;
        KD = HID; ND = DIM; kt = r >> 5; nt = r & 31;
    }

    __shared__ float tile[64][33];
    int tx = threadIdx.x & 31, ty = threadIdx.x >> 5;
    int k0 = kt * 64, n0 = nt * 32;
#pragma unroll
    for (int kr = ty; kr < 64; kr += 8)
        tile[kr][tx] = src[(size_t)(k0 + kr) * ND + n0 + tx];
    __syncthreads();
#pragma unroll
    for (int nr = ty; nr < 32; nr += 8) {
        __half2 hv = __floats2half2_rn(tile[2 * tx][nr], tile[2 * tx + 1][nr]);
        *(__half2*)(dst + (size_t)(n0 + nr) * KD + k0 + 2 * tx) = hv;
    }
}

// ---------------------------------------------------------------------------
// gating: one warp per token (uses ORIGINAL fp32 x)
// ---------------------------------------------------------------------------
__global__ void gating_kernel(const float* __restrict__ x,
                              const float* __restrict__ Wg,
                              const float* __restrict__ bg) {
    int warp = threadIdx.x >> 5;
    int lane = threadIdx.x & 31;
    int n = blockIdx.x * 8 + warp;
    if (n >= N_TOK) return;

    float acc[NEXP];
#pragma unroll
    for (int e = 0; e < NEXP; e++) acc[e] = 0.f;

    const float* xr = x + (size_t)n * DIM;
    for (int d = lane; d < DIM; d += 32) {
        float xv = xr[d];
        const float4* w4 = (const float4*)(Wg + (size_t)d * NEXP);
        float4 wa = w4[0];
        float4 wb = w4[1];
        acc[0] += xv * wa.x; acc[1] += xv * wa.y;
        acc[2] += xv * wa.z; acc[3] += xv * wa.w;
        acc[4] += xv * wb.x; acc[5] += xv * wb.y;
        acc[6] += xv * wb.z; acc[7] += xv * wb.w;
    }
#pragma unroll
    for (int e = 0; e < NEXP; e++) {
#pragma unroll
        for (int off = 16; off > 0; off >>= 1)
            acc[e] += __shfl_xor_sync(0xffffffff, acc[e], off);
    }

    if (lane == 0) {
        float lg[NEXP];
        float mx = -1e30f;
#pragma unroll
        for (int e = 0; e < NEXP; e++) {
            lg[e] = acc[e] + bg[e];
            mx = fmaxf(mx, lg[e]);
        }
        float s = 0.f;
#pragma unroll
        for (int e = 0; e < NEXP; e++) {
            lg[e] = expf(lg[e] - mx);
            s += lg[e];
        }
        float inv = 1.f / s;

        int i0 = 0; float v0 = -1.f;
#pragma unroll
        for (int e = 0; e < NEXP; e++) {
            float p = lg[e] * inv;
            if (p > v0) { v0 = p; i0 = e; }
        }
        int i1 = -1; float v1 = -1.f;
#pragma unroll
        for (int e = 0; e < NEXP; e++) {
            if (e == i0) continue;
            float p = lg[e] * inv;
            if (p > v1) { v1 = p; i1 = e; }
        }
        int p0 = atomicAdd(&g_cursor[i0], 1);
        g_token[i0 * N_TOK + p0] = n;
        g_gate [i0 * N_TOK + p0] = v0;
        g_dst  [i0 * N_TOK + p0] = 2 * n;
        int p1 = atomicAdd(&g_cursor[i1], 1);
        g_token[i1 * N_TOK + p1] = n;
        g_gate [i1 * N_TOK + p1] = v1;
        g_dst  [i1 * N_TOK + p1] = 2 * n + 1;
    }
}

// ---------------------------------------------------------------------------
// fp16 HMMA GEMM: CTA tile 64x128xK, 8 warps (2m x 4n), warptile 32x32.
// Target 3 CTAs/SM (launch_bounds(256,3) caps regs ~85).
//   MODE 0: A = x fp32 gathered by g_token (cvt inline) -> g_h1h (relu, half)
//   MODE 1: A = g_h1h                                   -> g_h2h (relu, half)
//   MODE 2: A = g_h2h                                   -> g_eoh[g_dst] (gate*relu)
// ---------------------------------------------------------------------------
template <int KDIM, int NMAT, int MODE>
__global__ void __launch_bounds__(256, 3)
gemm_mma(const float* __restrict__ Af,      // fp32 source (MODE 0)
         const __half* __restrict__ Ah,     // half source (MODE 1/2)
         const __half* __restrict__ Bt,     // [e][NMAT][KDIM] half weights
         const float* __restrict__ bias,
         __half* __restrict__ Out) {
    int e = blockIdx.z;
    int count = g_cursor[e];
    int m0 = blockIdx.x * BM;
    if (m0 >= count) return;
    int n0 = blockIdx.y * BN;

    __shared__ __align__(16) __half As[2][BM * LDA];
    __shared__ __align__(16) __half Bs[2][BN * LDB];
    __shared__ int rows[BM];

    int t = threadIdx.x;
    int lane = t & 31;
    int w = t >> 5;
    int wm = w & 1;       // 2 m-warps
    int wn = w >> 1;      // 4 n-warps

    const __half* A_eh = Ah + (size_t)e * N_TOK * HID;
    const __half* B_e  = Bt + (size_t)e * (size_t)KDIM * NMAT;

    if (MODE == 0 && t < BM) {
        int pos = m0 + t;
        if (pos >= count) pos = count - 1;
        rows[t] = g_token[e * N_TOK + pos];
    }
    __syncthreads();

    // load tasks: A 256 segs (1/thr), B 512 segs (2/thr); seg = 8 halves
    int a_row = t >> 2;             // 0..63
    int a_seg = (t & 3) * 8;
    int b_row[2], b_seg[2];
#pragma unroll
    for (int q = 0; q < 2; q++) {
        int s = t + 256 * q;
        b_row[q] = s >> 2;          // 0..127
        b_seg[q] = (s & 3) * 8;
    }
    const float*  a_srcf;
    const __half* a_srch;
    const __half* b_src[2];
    if (MODE == 0) a_srcf = Af + (size_t)rows[a_row] * KDIM;
    else           a_srch = A_eh + (size_t)(m0 + a_row) * KDIM;
#pragma unroll
    for (int q = 0; q < 2; q++)
        b_src[q] = B_e + (size_t)(n0 + b_row[q]) * KDIM;

    uint4 va, vb[2];
    auto load_regs = [&](int kt) {
        int k0 = kt * BK;
        if (MODE == 0) {
            float4 v0 = *(const float4*)(a_srcf + k0 + a_seg);
            float4 v1 = *(const float4*)(a_srcf + k0 + a_seg + 4);
            va.x = pack_h2(v0.x, v0.y);
            va.y = pack_h2(v0.z, v0.w);
            va.z = pack_h2(v1.x, v1.y);
            va.w = pack_h2(v1.z, v1.w);
        } else {
            va = *(const uint4*)(a_srch + k0 + a_seg);
        }
#pragma unroll
        for (int q = 0; q < 2; q++)
            vb[q] = *(const uint4*)(b_src[q] + k0 + b_seg[q]);
    };
    auto store_smem = [&](int buf) {
        *(uint4*)&As[buf][a_row * LDA + a_seg] = va;
#pragma unroll
        for (int q = 0; q < 2; q++)
            *(uint4*)&Bs[buf][b_row[q] * LDB + b_seg[q]] = vb[q];
    };

    unsigned asb[2], bsb[2];
#pragma unroll
    for (int b = 0; b < 2; b++) {
        asb[b] = (unsigned)__cvta_generic_to_shared(&As[b][0]);
        bsb[b] = (unsigned)__cvta_generic_to_shared(&Bs[b][0]);
    }
    int rsel = lane & 15;
    int ksel = (lane >> 4) * 8;

    float c[2][4][4];
#pragma unroll
    for (int mi = 0; mi < 2; mi++)
#pragma unroll
        for (int ni = 0; ni < 4; ni++)
#pragma unroll
            for (int r = 0; r < 4; r++) c[mi][ni][r] = 0.f;

    const int NK = KDIM / BK;
    load_regs(0);
    store_smem(0);
    __syncthreads();

    for (int kt = 0; kt < NK; kt++) {
        int cur = kt & 1;
        if (kt + 1 < NK) load_regs(kt + 1);

#pragma unroll
        for (int ka = 0; ka < BK; ka += 16) {
            unsigned afrag[2][4], bfrag[2][4];
#pragma unroll
            for (int mi = 0; mi < 2; mi++) {
                unsigned addr = asb[cur] +
                    ((wm * 32 + mi * 16 + rsel) * LDA + ka + ksel) * 2;
                ldsm_x4(addr, afrag[mi]);
            }
#pragma unroll
            for (int p = 0; p < 2; p++) {
                unsigned addr = bsb[cur] +
                    ((wn * 32 + p * 16 + rsel) * LDB + ka + ksel) * 2;
                ldsm_x4(addr, bfrag[p]);
            }
#pragma unroll
            for (int mi = 0; mi < 2; mi++) {
#pragma unroll
                for (int p = 0; p < 2; p++) {
                    mma_f16(c[mi][2 * p + 0], afrag[mi], bfrag[p][0], bfrag[p][2]);
                    mma_f16(c[mi][2 * p + 1], afrag[mi], bfrag[p][1], bfrag[p][3]);
                }
            }
        }

        if (kt + 1 < NK) store_smem((kt + 1) & 1);
        __syncthreads();
    }

    // ---- epilogue: packed half2 stores ----
    const float* bias_e = bias + (size_t)e * NMAT;
    int gg = lane >> 2;
    int tc = lane & 3;

#pragma unroll
    for (int mi = 0; mi < 2; mi++) {
#pragma unroll
        for (int h = 0; h < 2; h++) {
            int m_local = wm * 32 + mi * 16 + gg + h * 8;
            int pos = m0 + m_local;
            if (pos < count) {
                float gate = 1.f;
                size_t orow;
                if (MODE == 2) {
                    gate = g_gate[e * N_TOK + pos];
                    orow = (size_t)g_dst[e * N_TOK + pos] * DIM;
                } else {
                    orow = ((size_t)e * N_TOK + pos) * HID;
                }
#pragma unroll
                for (int ni = 0; ni < 4; ni++) {
                    int n = n0 + wn * 32 + ni * 8 + tc * 2;
                    float v0 = c[mi][ni][h * 2 + 0];
                    float v1 = c[mi][ni][h * 2 + 1];
                    float2 bv = *(const float2*)(bias_e + n);
                    float o0, o1;
                    if (MODE == 2) {
                        o0 = gate * fmaxf(v0 + bv.x, 0.f);
                        o1 = gate * fmaxf(v1 + bv.y, 0.f);
                    } else {
                        o0 = fmaxf(v0 + bv.x, 0.f);
                        o1 = fmaxf(v1 + bv.y, 0.f);
                    }
                    *(unsigned*)(Out + orow + n) = pack_h2(o0, o1);
                }
            }
        }
    }
}

// ---------------------------------------------------------------------------
// combine: out[n,:] = eo[2n,:] + eo[2n+1,:]  (token-major, pure streaming)
// ---------------------------------------------------------------------------
__global__ void combine_kernel(float* __restrict__ out) {
    const __half* eo = g_eoh;
    int tot = N_TOK * (DIM / 8);
    int stride = gridDim.x * blockDim.x;
    for (int idx = blockIdx.x * blockDim.x + threadIdx.x; idx < tot; idx += stride) {
        int n = idx >> 7;           // DIM/8 = 128
        int cidx = (idx & 127) * 8;
        uint4 a4 = *(const uint4*)(eo + (size_t)(2 * n)     * DIM + cidx);
        uint4 b4 = *(const uint4*)(eo + (size_t)(2 * n + 1) * DIM + cidx);
        const __half2* ah = (const __half2*)&a4;
        const __half2* bh = (const __half2*)&b4;
        float4 o0, o1;
        float2 t0 = __half22float2(ah[0]), u0 = __half22float2(bh[0]);
        float2 t1 = __half22float2(ah[1]), u1 = __half22float2(bh[1]);
        float2 t2 = __half22float2(ah[2]), u2 = __half22float2(bh[2]);
        float2 t3 = __half22float2(ah[3]), u3 = __half22float2(bh[3]);
        o0.x = t0.x + u0.x; o0.y = t0.y + u0.y;
        o0.z = t1.x + u1.x; o0.w = t1.y + u1.y;
        o1.x = t2.x + u2.x; o1.y = t2.y + u2.y;
        o1.z = t3.x + u3.x; o1.w = t3.y + u3.y;
        float* op = out + (size_t)n * DIM + cidx;
        *(float4*)(op + 0) = o0;
        *(float4*)(op + 4) = o1;
    }
}

// ---------------------------------------------------------------------------
extern "C" void kernel_launch(void* const* d_in, const int* in_sizes, int n_in,
                              void* d_out, int out_size) {
    const float* x  = (const float*)d_in[0];
    const float* Wg = (const float*)d_in[1];
    const float* bg = (const float*)d_in[2];
    const float* W1 = (const float*)d_in[3];
    const float* b1 = (const float*)d_in[4];
    const float* W2 = (const float*)d_in[5];
    const float* b2 = (const float*)d_in[6];
    const float* W3 = (const float*)d_in[7];
    const float* b3 = (const float*)d_in[8];
    float* out = (float*)d_out;

    __half *h1, *h2, *eo, *w1t, *w2t, *w3t;
    cudaGetSymbolAddress((void**)&h1,  g_h1h);
    cudaGetSymbolAddress((void**)&h2,  g_h2h);
    cudaGetSymbolAddress((void**)&eo,  g_eoh);
    cudaGetSymbolAddress((void**)&w1t, g_w1t);
    cudaGetSymbolAddress((void**)&w2t, g_w2t);
    cudaGetSymbolAddress((void**)&w3t, g_w3t);

    prep_kernel<<<dim3(288, 1, NEXP), 256>>>(W1, W2, W3, w1t, w2t, w3t);
    gating_kernel<<<N_TOK / 8, 256>>>(x, Wg, bg);

    gemm_mma<DIM, HID, 0><<<dim3(N_TOK / BM, HID / BN, NEXP), 256>>>(x, h1, w1t, b1, h1);
    gemm_mma<HID, HID, 1><<<dim3(N_TOK / BM, HID / BN, NEXP), 256>>>(nullptr, h1, w2t, b2, h2);
    gemm_mma<HID, DIM, 2><<<dim3(N_TOK / BM, DIM / BN, NEXP), 256>>>(nullptr, h2, w3t, b3, eo);
    combine_kernel<<<2048, 256>>>(out);
}

// round 14
// speedup vs baseline: 1.2080x; 1.2080x over previous
#include <cuda_runtime.h>
#include <cuda_fp16.h>
#include <cstdint>

#define N_TOK 8192
#define DIM   1024
#define NEXP  8
#define HID   256

#define BM 128
#define BN 128
#define BK 64    // K elements per tile (4 x k16 mma steps), filled in 2 groups
#define LDA 72   // padded row stride in halves: 144B (36 words, %32=4) conflict-free
#define LDB 72

// ---- static device scratch (no allocations allowed) ----
__device__ int    g_cursor[NEXP];
__device__ int    g_token[NEXP * N_TOK];
__device__ float  g_gate [NEXP * N_TOK];
__device__ int    g_dst  [NEXP * N_TOK];               // eo row = 2*token+which
__device__ __half g_xh [(size_t)N_TOK * DIM];          // 16 MB (x in half)
__device__ __half g_h1h[(size_t)NEXP * N_TOK * HID];   // 32 MB
__device__ __half g_h2h[(size_t)NEXP * N_TOK * HID];   // 32 MB
__device__ __half g_eoh[(size_t)2 * N_TOK * DIM];      // 32 MB token-major
__device__ __half g_w1t[(size_t)NEXP * DIM * HID];     // 4 MB  [e][N][K] half
__device__ __half g_w2t[(size_t)NEXP * HID * HID];     // 1 MB
__device__ __half g_w3t[(size_t)NEXP * HID * DIM];     // 4 MB

// ---------------------------------------------------------------------------
__device__ __forceinline__ void ldsm_x4(unsigned addr, unsigned r[4]) {
    asm volatile("ldmatrix.sync.aligned.m8n8.x4.shared.b16 {%0,%1,%2,%3}, [%4];"
                 : "=r"(r[0]), "=r"(r[1]), "=r"(r[2]), "=r"(r[3]) : "r"(addr));
}
__device__ __forceinline__ void mma_f16(float c[4], const unsigned a[4],
                                        unsigned b0, unsigned b1) {
    asm volatile(
        "mma.sync.aligned.m16n8k16.row.col.f32.f16.f16.f32 "
        "{%0,%1,%2,%3}, {%4,%5,%6,%7}, {%8,%9}, {%0,%1,%2,%3};"
        : "+f"(c[0]), "+f"(c[1]), "+f"(c[2]), "+f"(c[3])
        : "r"(a[0]), "r"(a[1]), "r"(a[2]), "r"(a[3]), "r"(b0), "r"(b1));
}
__device__ __forceinline__ unsigned pack_h2(float x, float y) {
    __half2 h = __floats2half2_rn(x, y);
    return *(unsigned*)&h;
}

// ---------------------------------------------------------------------------
// prep: zero cursors + weights -> [e][N][K] half + x -> half
// grid (544, 1, 8): bid<288 = weight transpose tiles; bid in [288,544) = x segs
// ---------------------------------------------------------------------------
__global__ void prep_kernel(const float* __restrict__ x,
                            const float* __restrict__ W1,
                            const float* __restrict__ W2,
                            const float* __restrict__ W3,
                            __half* __restrict__ xh,
                            __half* __restrict__ w1t,
                            __half* __restrict__ w2t,
                            __half* __restrict__ w3t) {
    if (blockIdx.x == 0 && blockIdx.z == 0 && threadIdx.x < NEXP)
        g_cursor[threadIdx.x] = 0;

    int e = blockIdx.z;
    int bid = blockIdx.x;

    if (bid >= 288) {
        // x conversion: 2048 segments of 4096 floats; this z-slice owns 256
        int seg = e * 256 + (bid - 288);
        const float4* s4 = (const float4*)(x + (size_t)seg * 4096);
        __half* d = xh + (size_t)seg * 4096;
#pragma unroll
        for (int i = 0; i < 4; i++) {
            int idx = threadIdx.x + i * 256;          // float4 index within seg
            float4 v = s4[idx];
            unsigned lo = pack_h2(v.x, v.y);
            unsigned hi = pack_h2(v.z, v.w);
            *(uint2*)(d + idx * 4) = make_uint2(lo, hi);
        }
        return;
    }

    const float* src;
    __half* dst;
    int KD, ND, kt, nt;
    if (bid < 128) {
        src = W1 + (size_t)e * DIM * HID; dst = w1t + (size_t)e * DIM * HID;
        KD = DIM; ND = HID; kt = bid >> 3; nt = bid & 7;
    } else if (bid < 160) {
        int r = bid - 128;
        src = W2 + (size_t)e * HID * HID; dst = w2t + (size_t)e * HID * HID;
        KD = HID; ND = HID; kt = r >> 3; nt = r & 7;
    } else {
        int r = bid - 160;
        src = W3 + (size_t)e * HID * DIM; dst = w3t + (size_t)e * HID * DIM;
        KD = HID; ND = DIM; kt = r >> 5; nt = r & 31;
    }

    __shared__ float tile[64][33];
    int tx = threadIdx.x & 31, ty = threadIdx.x >> 5;
    int k0 = kt * 64, n0 = nt * 32;
#pragma unroll
    for (int kr = ty; kr < 64; kr += 8)
        tile[kr][tx] = src[(size_t)(k0 + kr) * ND + n0 + tx];
    __syncthreads();
#pragma unroll
    for (int nr = ty; nr < 32; nr += 8) {
        __half2 hv = __floats2half2_rn(tile[2 * tx][nr], tile[2 * tx + 1][nr]);
        *(__half2*)(dst + (size_t)(n0 + nr) * KD + k0 + 2 * tx) = hv;
    }
}

// ---------------------------------------------------------------------------
// gating: one warp per token (uses ORIGINAL fp32 x)
// ---------------------------------------------------------------------------
__global__ void gating_kernel(const float* __restrict__ x,
                              const float* __restrict__ Wg,
                              const float* __restrict__ bg) {
    int warp = threadIdx.x >> 5;
    int lane = threadIdx.x & 31;
    int n = blockIdx.x * 8 + warp;
    if (n >= N_TOK) return;

    float acc[NEXP];
#pragma unroll
    for (int e = 0; e < NEXP; e++) acc[e] = 0.f;

    const float* xr = x + (size_t)n * DIM;
    for (int d = lane; d < DIM; d += 32) {
        float xv = xr[d];
        const float4* w4 = (const float4*)(Wg + (size_t)d * NEXP);
        float4 wa = w4[0];
        float4 wb = w4[1];
        acc[0] += xv * wa.x; acc[1] += xv * wa.y;
        acc[2] += xv * wa.z; acc[3] += xv * wa.w;
        acc[4] += xv * wb.x; acc[5] += xv * wb.y;
        acc[6] += xv * wb.z; acc[7] += xv * wb.w;
    }
#pragma unroll
    for (int e = 0; e < NEXP; e++) {
#pragma unroll
        for (int off = 16; off > 0; off >>= 1)
            acc[e] += __shfl_xor_sync(0xffffffff, acc[e], off);
    }

    if (lane == 0) {
        float lg[NEXP];
        float mx = -1e30f;
#pragma unroll
        for (int e = 0; e < NEXP; e++) {
            lg[e] = acc[e] + bg[e];
            mx = fmaxf(mx, lg[e]);
        }
        float s = 0.f;
#pragma unroll
        for (int e = 0; e < NEXP; e++) {
            lg[e] = expf(lg[e] - mx);
            s += lg[e];
        }
        float inv = 1.f / s;

        int i0 = 0; float v0 = -1.f;
#pragma unroll
        for (int e = 0; e < NEXP; e++) {
            float p = lg[e] * inv;
            if (p > v0) { v0 = p; i0 = e; }
        }
        int i1 = -1; float v1 = -1.f;
#pragma unroll
        for (int e = 0; e < NEXP; e++) {
            if (e == i0) continue;
            float p = lg[e] * inv;
            if (p > v1) { v1 = p; i1 = e; }
        }
        int p0 = atomicAdd(&g_cursor[i0], 1);
        g_token[i0 * N_TOK + p0] = n;
        g_gate [i0 * N_TOK + p0] = v0;
        g_dst  [i0 * N_TOK + p0] = 2 * n;
        int p1 = atomicAdd(&g_cursor[i1], 1);
        g_token[i1 * N_TOK + p1] = n;
        g_gate [i1 * N_TOK + p1] = v1;
        g_dst  [i1 * N_TOK + p1] = 2 * n + 1;
    }
}

// ---------------------------------------------------------------------------
// fp16 HMMA GEMM: CTA tile 128x128xK, 8 warps (4m x 2n), warptile 32x64.
// BK=64 double-buffered, filled in two 16-reg staging groups per tile
// (halves the __syncthreads count vs BK=32 at identical register pressure).
//   MODE 0: A = g_xh gathered by g_token -> g_h1h (relu, half)
//   MODE 1: A = g_h1h                    -> g_h2h (relu, half)
//   MODE 2: A = g_h2h                    -> g_eoh[g_dst] (gate*relu, half)
// ---------------------------------------------------------------------------
#define STAGE_H (BM * LDA)                 // halves per operand per buffer
#define GEMM_SMEM (4 * STAGE_H * 2)        // As x2 + Bs x2, bytes = 73728

template <int KDIM, int NMAT, int MODE>
__global__ void __launch_bounds__(256, 2)
gemm_mma(const __half* __restrict__ Ah,     // A source (xh for MODE 0)
         const __half* __restrict__ Bt,     // [e][NMAT][KDIM] half weights
         const float* __restrict__ bias,
         __half* __restrict__ Out) {
    int e = blockIdx.z;
    int count = g_cursor[e];
    int m0 = blockIdx.x * BM;
    if (m0 >= count) return;
    int n0 = blockIdx.y * BN;

    extern __shared__ __align__(16) __half smem[];
    __half* As = smem;                      // 2 x STAGE_H
    __half* Bs = smem + 2 * STAGE_H;        // 2 x STAGE_H
    __shared__ int rows[BM];

    int t = threadIdx.x;
    int lane = t & 31;
    int w = t >> 5;
    int wm = w & 3;       // 4 m-warps
    int wn = w >> 2;      // 2 n-warps

    const __half* A_e = (MODE == 0) ? Ah : Ah + (size_t)e * N_TOK * HID;
    const __half* B_e = Bt + (size_t)e * (size_t)KDIM * NMAT;

    if (MODE == 0 && t < BM) {
        int pos = m0 + t;
        if (pos >= count) pos = count - 1;
        rows[t] = g_token[e * N_TOK + pos];
    }
    __syncthreads();

    // load tasks per GROUP (32 k-cols): 512 segs of 8 halves, 2/thread
    int lr[2], lseg[2];
#pragma unroll
    for (int q = 0; q < 2; q++) {
        int s = t + 256 * q;
        lr[q]   = s >> 2;           // 0..127
        lseg[q] = (s & 3) * 8;      // 0,8,16,24 within the 32-col group
    }
    const __half* a_src[2];
    const __half* b_src[2];
#pragma unroll
    for (int q = 0; q < 2; q++) {
        if (MODE == 0) a_src[q] = A_e + (size_t)rows[lr[q]] * KDIM;
        else           a_src[q] = A_e + (size_t)(m0 + lr[q]) * KDIM;
        b_src[q] = B_e + (size_t)(n0 + lr[q]) * KDIM;
    }

    uint4 va[2], vb[2];
    auto load_group = [&](int kt, int g) {
        int k0 = kt * BK + g * 32;
#pragma unroll
        for (int q = 0; q < 2; q++) {
            va[q] = *(const uint4*)(a_src[q] + k0 + lseg[q]);
            vb[q] = *(const uint4*)(b_src[q] + k0 + lseg[q]);
        }
    };
    auto store_group = [&](int buf, int g) {
#pragma unroll
        for (int q = 0; q < 2; q++) {
            *(uint4*)&As[buf * STAGE_H + lr[q] * LDA + g * 32 + lseg[q]] = va[q];
            *(uint4*)&Bs[buf * STAGE_H + lr[q] * LDB + g * 32 + lseg[q]] = vb[q];
        }
    };

    unsigned asb[2], bsb[2];
#pragma unroll
    for (int b = 0; b < 2; b++) {
        asb[b] = (unsigned)__cvta_generic_to_shared(As + b * STAGE_H);
        bsb[b] = (unsigned)__cvta_generic_to_shared(Bs + b * STAGE_H);
    }
    int rsel = lane & 15;
    int ksel = (lane >> 4) * 8;

    float c[2][8][4];
#pragma unroll
    for (int mi = 0; mi < 2; mi++)
#pragma unroll
        for (int ni = 0; ni < 8; ni++)
#pragma unroll
            for (int r = 0; r < 4; r++) c[mi][ni][r] = 0.f;

    // one ka-step (16 k-cols) of the warptile from buffer cur
    auto compute_ka = [&](int cur, int ka) {
        unsigned afrag[2][4], bfrag[4][4];
#pragma unroll
        for (int mi = 0; mi < 2; mi++) {
            unsigned addr = asb[cur] +
                ((wm * 32 + mi * 16 + rsel) * LDA + ka + ksel) * 2;
            ldsm_x4(addr, afrag[mi]);
        }
#pragma unroll
        for (int p = 0; p < 4; p++) {
            unsigned addr = bsb[cur] +
                ((wn * 64 + p * 16 + rsel) * LDB + ka + ksel) * 2;
            ldsm_x4(addr, bfrag[p]);
        }
#pragma unroll
        for (int mi = 0; mi < 2; mi++) {
#pragma unroll
            for (int p = 0; p < 4; p++) {
                mma_f16(c[mi][2 * p + 0], afrag[mi], bfrag[p][0], bfrag[p][2]);
                mma_f16(c[mi][2 * p + 1], afrag[mi], bfrag[p][1], bfrag[p][3]);
            }
        }
    };

    const int NK = KDIM / BK;
    // prologue: fill buffer 0 (both groups)
    load_group(0, 0); store_group(0, 0);
    load_group(0, 1); store_group(0, 1);
    __syncthreads();

    for (int kt = 0; kt < NK; kt++) {
        int cur = kt & 1;
        int nxt = cur ^ 1;
        bool more = (kt + 1 < NK);

        if (more) load_group(kt + 1, 0);
        compute_ka(cur, 0);
        compute_ka(cur, 16);
        if (more) {
            store_group(nxt, 0);
            load_group(kt + 1, 1);
        }
        compute_ka(cur, 32);
        compute_ka(cur, 48);
        if (more) store_group(nxt, 1);
        __syncthreads();
    }

    // ---- epilogue: packed half2 stores ----
    const float* bias_e = bias + (size_t)e * NMAT;
    int gg = lane >> 2;
    int tc = lane & 3;

#pragma unroll
    for (int mi = 0; mi < 2; mi++) {
#pragma unroll
        for (int h = 0; h < 2; h++) {
            int m_local = wm * 32 + mi * 16 + gg + h * 8;
            int pos = m0 + m_local;
            if (pos < count) {
                float gate = 1.f;
                size_t orow;
                if (MODE == 2) {
                    gate = g_gate[e * N_TOK + pos];
                    orow = (size_t)g_dst[e * N_TOK + pos] * DIM;
                } else {
                    orow = ((size_t)e * N_TOK + pos) * HID;
                }
#pragma unroll
                for (int ni = 0; ni < 8; ni++) {
                    int n = n0 + wn * 64 + ni * 8 + tc * 2;
                    float v0 = c[mi][ni][h * 2 + 0];
                    float v1 = c[mi][ni][h * 2 + 1];
                    float2 bv = *(const float2*)(bias_e + n);
                    float o0, o1;
                    if (MODE == 2) {
                        o0 = gate * fmaxf(v0 + bv.x, 0.f);
                        o1 = gate * fmaxf(v1 + bv.y, 0.f);
                    } else {
                        o0 = fmaxf(v0 + bv.x, 0.f);
                        o1 = fmaxf(v1 + bv.y, 0.f);
                    }
                    *(unsigned*)(Out + orow + n) = pack_h2(o0, o1);
                }
            }
        }
    }
}

// ---------------------------------------------------------------------------
// combine: out[n,:] = eo[2n,:] + eo[2n+1,:]  (token-major, pure streaming)
// ---------------------------------------------------------------------------
__global__ void combine_kernel(float* __restrict__ out) {
    const __half* eo = g_eoh;
    int tot = N_TOK * (DIM / 8);
    int stride = gridDim.x * blockDim.x;
    for (int idx = blockIdx.x * blockDim.x + threadIdx.x; idx < tot; idx += stride) {
        int n = idx >> 7;           // DIM/8 = 128
        int cidx = (idx & 127) * 8;
        uint4 a4 = *(const uint4*)(eo + (size_t)(2 * n)     * DIM + cidx);
        uint4 b4 = *(const uint4*)(eo + (size_t)(2 * n + 1) * DIM + cidx);
        const __half2* ah = (const __half2*)&a4;
        const __half2* bh = (const __half2*)&b4;
        float4 o0, o1;
        float2 t0 = __half22float2(ah[0]), u0 = __half22float2(bh[0]);
        float2 t1 = __half22float2(ah[1]), u1 = __half22float2(bh[1]);
        float2 t2 = __half22float2(ah[2]), u2 = __half22float2(bh[2]);
        float2 t3 = __half22float2(ah[3]), u3 = __half22float2(bh[3]);
        o0.x = t0.x + u0.x; o0.y = t0.y + u0.y;
        o0.z = t1.x + u1.x; o0.w = t1.y + u1.y;
        o1.x = t2.x + u2.x; o1.y = t2.y + u2.y;
        o1.z = t3.x + u3.x; o1.w = t3.y + u3.y;
        float* op = out + (size_t)n * DIM + cidx;
        *(float4*)(op + 0) = o0;
        *(float4*)(op + 4) = o1;
    }
}

// ---------------------------------------------------------------------------
extern "C" void kernel_launch(void* const* d_in, const int* in_sizes, int n_in,
                              void* d_out, int out_size) {
    const float* x  = (const float*)d_in[0];
    const float* Wg = (const float*)d_in[1];
    const float* bg = (const float*)d_in[2];
    const float* W1 = (const float*)d_in[3];
    const float* b1 = (const float*)d_in[4];
    const float* W2 = (const float*)d_in[5];
    const float* b2 = (const float*)d_in[6];
    const float* W3 = (const float*)d_in[7];
    const float* b3 = (const float*)d_in[8];
    float* out = (float*)d_out;

    __half *xh, *h1, *h2, *eo, *w1t, *w2t, *w3t;
    cudaGetSymbolAddress((void**)&xh,  g_xh);
    cudaGetSymbolAddress((void**)&h1,  g_h1h);
    cudaGetSymbolAddress((void**)&h2,  g_h2h);
    cudaGetSymbolAddress((void**)&eo,  g_eoh);
    cudaGetSymbolAddress((void**)&w1t, g_w1t);
    cudaGetSymbolAddress((void**)&w2t, g_w2t);
    cudaGetSymbolAddress((void**)&w3t, g_w3t);

    cudaFuncSetAttribute(gemm_mma<DIM, HID, 0>,
                         cudaFuncAttributeMaxDynamicSharedMemorySize, GEMM_SMEM);
    cudaFuncSetAttribute(gemm_mma<HID, HID, 1>,
                         cudaFuncAttributeMaxDynamicSharedMemorySize, GEMM_SMEM);
    cudaFuncSetAttribute(gemm_mma<HID, DIM, 2>,
                         cudaFuncAttributeMaxDynamicSharedMemorySize, GEMM_SMEM);

    prep_kernel<<<dim3(544, 1, NEXP), 256>>>(x, W1, W2, W3, xh, w1t, w2t, w3t);
    gating_kernel<<<N_TOK / 8, 256>>>(x, Wg, bg);

    gemm_mma<DIM, HID, 0><<<dim3(N_TOK / BM, HID / BN, NEXP), 256, GEMM_SMEM>>>(xh, w1t, b1, h1);
    gemm_mma<HID, HID, 1><<<dim3(N_TOK / BM, HID / BN, NEXP), 256, GEMM_SMEM>>>(h1, w2t, b2, h2);
    gemm_mma<HID, DIM, 2><<<dim3(N_TOK / BM, DIM / BN, NEXP), 256, GEMM_SMEM>>>(h2, w3t, b3, eo);
    combine_kernel<<<2048, 256>>>(out);
}